// round 15
// baseline (speedup 1.0000x reference)
#include <cuda_runtime.h>
#include <cuda_fp16.h>
#include <cstdint>
#include <math.h>

#define NN   2000
#define NNP  2048      // padded j-dim for WhT (covers 32 tiles of 64)
#define BB   8
#define HH   4
#define DIN  64
#define DH   128
#define BH   32        // BB*HH
#define RL   50
#define MT   128       // attention M tile (rows per CTA)
#define NMT  16        // ceil(2000/128)
#define DHALF 64       // d columns per CTA (d-split)
#define JT2  64        // attention j tile
#define NJT2 32        // 2048/64
#define LOG2E 1.4426950408889634f
#define LN_EPS 1e-5f
#define BPAD 40        // k_proj smem row stride in halves
#define BPAD2 72       // k_attn smem tile row stride in halves (64 + 8 pad)
#define WPK  520       // WpT row stride in halves (512 + 8 pad)
#define ONES2 0x3C003C00u   // two f16 1.0

// ---------------- device scratch (static; zero-initialized at load) ---------
__device__ __half   g_WhTH[(size_t)BH*DH*NNP];   // [(bh*128+d)][j] transposed Wh, f16
__device__ float    g_f1 [BH*NN];
__device__ float    g_f2 [BH*NN];
__device__ unsigned g_adjT[64*2048];             // [tile32][row] packed adjacency
__device__ int      g_hasnbr[NN];
__device__ __half   g_hpH[(size_t)BB*NN*HH*DH];  // elu(h_prime) node-major, f16
__device__ __half   g_WpTH[DH*WPK];              // WpT [n][k] f16
__device__ float    g_enc[(size_t)BB*NN*DH];
__device__ float    g_part[BB*16*DH];            // pooling partials

// ---------------- helpers ----------------------------------------------------
__device__ __forceinline__ uint32_t packh2(float lo, float hi){
    __half2 h = __floats2half2_rn(lo, hi);
    return *reinterpret_cast<uint32_t*>(&h);
}
__device__ __forceinline__ uint32_t ex2h2(uint32_t a){
    uint32_t r; asm("ex2.approx.f16x2 %0, %1;" : "=r"(r) : "r"(a)); return r;
}
__device__ __forceinline__ uint32_t prmtb(uint32_t a, uint32_t b, uint32_t s){
    uint32_t d; asm("prmt.b32 %0, %1, %2, %3;" : "=r"(d) : "r"(a), "r"(b), "r"(s));
    return d;
}
__device__ __forceinline__ uint32_t smem_u32(const void* p){
    uint32_t a;
    asm("{ .reg .u64 t; cvta.to.shared.u64 t, %1; cvt.u32.u64 %0, t; }"
        : "=r"(a) : "l"(p));
    return a;
}
// packed f32x2 (lanewise IEEE-identical to scalar add/fma)
__device__ __forceinline__ unsigned long long add2(unsigned long long a,
                                                   unsigned long long b){
    unsigned long long d;
    asm("add.rn.f32x2 %0, %1, %2;" : "=l"(d) : "l"(a), "l"(b));
    return d;
}
__device__ __forceinline__ unsigned long long ffma2(unsigned long long a,
                                                    unsigned long long b,
                                                    unsigned long long c){
    unsigned long long d;
    asm("fma.rn.f32x2 %0, %1, %2, %3;" : "=l"(d) : "l"(a), "l"(b), "l"(c));
    return d;
}
__device__ __forceinline__ unsigned long long packdup(float p){
    unsigned long long d;
    asm("mov.b64 %0, {%1, %2};" : "=l"(d) : "f"(p), "f"(p));
    return d;
}
__device__ __forceinline__ float u64lo(unsigned long long v){
    return __uint_as_float((unsigned)(v & 0xffffffffULL));
}
__device__ __forceinline__ float u64hi(unsigned long long v){
    return __uint_as_float((unsigned)(v >> 32));
}
__device__ __forceinline__ void mma_f16(float* c, const uint32_t* a,
                                        uint32_t b0, uint32_t b1){
    asm volatile("mma.sync.aligned.m16n8k16.row.col.f32.f16.f16.f32 "
        "{%0,%1,%2,%3}, {%4,%5,%6,%7}, {%8,%9}, {%0,%1,%2,%3};"
        : "+f"(c[0]), "+f"(c[1]), "+f"(c[2]), "+f"(c[3])
        : "r"(a[0]), "r"(a[1]), "r"(a[2]), "r"(a[3]), "r"(b0), "r"(b1));
}
__device__ __forceinline__ void ldsm_x4(uint32_t& r0, uint32_t& r1,
                                        uint32_t& r2, uint32_t& r3, uint32_t a){
    asm volatile("ldmatrix.sync.aligned.m8n8.x4.shared.b16 {%0,%1,%2,%3}, [%4];"
        : "=r"(r0), "=r"(r1), "=r"(r2), "=r"(r3) : "r"(a));
}
#define CPA16(s,g)   asm volatile("cp.async.cg.shared.global [%0], [%1], 16;" :: "r"(s), "l"(g))
#define CPA_COMMIT() asm volatile("cp.async.commit_group;" ::: "memory")
#define CPA_WAIT0()  asm volatile("cp.async.wait_group 0;" ::: "memory")

// ================= K0: pack adjacency (transposed) + hasnbr =================
__global__ __launch_bounds__(256) void k_pack(const int* __restrict__ adj){
    int i = blockIdx.x;
    int t = threadIdx.x;
    int w = t >> 5, lane = t & 31;
    __shared__ unsigned orr;
    if (t == 0) orr = 0u;
    __syncthreads();
    unsigned wor = 0u;
    for (int g = w; g < 64; g += 8){
        int j = g*32 + lane;
        int v = (j < NN) ? (adj[(size_t)i*NN + j] > 0) : 0;
        unsigned word = __ballot_sync(0xffffffffu, v != 0);
        if (lane == 0){ g_adjT[g*2048 + i] = word; wor |= word; }
    }
    if (lane == 0 && wor) atomicOr(&orr, 1u);
    __syncthreads();
    if (t == 0) g_hasnbr[i] = (orr != 0u);
}

// ================= K1: WhT = (X @ W_heads)^T (f16)  (+ f1, f2) ==============
__global__ __launch_bounds__(256) void k_wh(const float* __restrict__ nf,
                                            const float* __restrict__ Wheads,
                                            const float* __restrict__ a1,
                                            const float* __restrict__ a2){
    __shared__ __align__(16) float Ws[DIN*DH];
    __shared__ float Xs[32][DIN+1];
    __shared__ float a1s[DH], a2s[DH];
    __shared__ float f1p[32][17], f2p[32][17];

    int bh = blockIdx.y;
    int t = threadIdx.x;
    int h  = bh & 3, b = bh >> 2;
    int rowbase = blockIdx.x * 32;

    const float* Wg = Wheads + (size_t)h*DIN*DH;
    for (int i = t; i < DIN*DH; i += 256) Ws[i] = Wg[i];
    if (t < DH){ a1s[t] = a1[h*DH+t]; a2s[t] = a2[h*DH+t]; }
    for (int i = t; i < 32*DIN; i += 256){
        int r = i >> 6, d = i & 63;
        int row = rowbase + r;
        Xs[r][d] = (row < NN) ? nf[((size_t)b*NN + row)*DIN + d] : 0.f;
    }
    __syncthreads();

    int tr = t >> 4, tc = t & 15;
    int r0 = tr*2, c0 = tc*8;
    unsigned long long acc2[2][4];
    #pragma unroll
    for (int r = 0; r < 2; r++)
        #pragma unroll
        for (int cc = 0; cc < 4; cc++) acc2[r][cc] = 0ull;

    #pragma unroll 4
    for (int k = 0; k < DIN; k++){
        unsigned long long x0p = packdup(Xs[r0][k]);
        unsigned long long x1p = packdup(Xs[r0+1][k]);
        const unsigned long long* wrow =
            (const unsigned long long*)&Ws[k*DH + c0];
        #pragma unroll
        for (int cc = 0; cc < 4; cc++){
            unsigned long long wp = wrow[cc];
            acc2[0][cc] = ffma2(x0p, wp, acc2[0][cc]);
            acc2[1][cc] = ffma2(x1p, wp, acc2[1][cc]);
        }
    }
    float acc[2][8];
    #pragma unroll
    for (int r = 0; r < 2; r++)
        #pragma unroll
        for (int cc = 0; cc < 4; cc++){
            acc[r][2*cc]   = u64lo(acc2[r][cc]);
            acc[r][2*cc+1] = u64hi(acc2[r][cc]);
        }

    #pragma unroll
    for (int r = 0; r < 2; r++){
        float p1 = 0.f, p2 = 0.f;
        #pragma unroll
        for (int c = 0; c < 8; c++){
            p1 = fmaf(acc[r][c], a1s[c0+c], p1);
            p2 = fmaf(acc[r][c], a2s[c0+c], p2);
        }
        f1p[r0+r][tc] = p1;
        f2p[r0+r][tc] = p2;
    }
    __syncthreads();
    if (t < 32){
        float s1 = 0.f, s2 = 0.f;
        #pragma unroll
        for (int c = 0; c < 16; c++){ s1 += f1p[t][c]; s2 += f2p[t][c]; }
        int row = rowbase + t;
        if (row < NN){ g_f1[bh*NN+row] = s1; g_f2[bh*NN+row] = s2; }
    }
    float* Ts = Ws;   // [d][r] padded: d*33 + r
    #pragma unroll
    for (int r = 0; r < 2; r++)
        #pragma unroll
        for (int c = 0; c < 8; c++)
            Ts[(c0+c)*33 + (r0+r)] = acc[r][c];
    __syncthreads();
    {
        int d = t >> 1, hf = t & 1;
        int colbase = rowbase + hf*16;
        const float* src = &Ts[d*33 + hf*16];
        __half* dst = &g_WhTH[((size_t)bh*DH + d)*NNP + colbase];
        if (colbase + 16 <= NN){
            uint32_t u[8];
            #pragma unroll
            for (int q = 0; q < 8; q++) u[q] = packh2(src[2*q], src[2*q+1]);
            *(uint4*)dst       = make_uint4(u[0],u[1],u[2],u[3]);
            *(uint4*)(dst + 8) = make_uint4(u[4],u[5],u[6],u[7]);
        } else {
            for (int i = 0; i < 16; i++)
                if (colbase + i < NN) dst[i] = __float2half_rn(src[i]);
        }
    }
}

// ================= K2: WpT f16 conversion (keeps k_attn at profiled slot) ===
__global__ __launch_bounds__(256) void k_wpcvt(const float* __restrict__ Wp){
    int id = blockIdx.x*256 + threadIdx.x;
    if (id < 512*128){
        int k = id >> 7, n = id & 127;
        g_WpTH[n*WPK + k] = __float2half_rn(Wp[id]);
    }
}

// ======= K3: fused attention, d-split (CTA = 128 rows x 64 d), occ 3 ========
__global__ __launch_bounds__(256,3) void k_attn(){
    __shared__ __align__(16) float  f2a[NNP];
    __shared__ __align__(16) __half Whs[2][DHALF*BPAD2];   // 2 x 9216 B
    __shared__ float  redm[8];

    int by = blockIdx.y;
    int bh = by >> 1, dh = by & 1;      // pair CTAs of same bh adjacent
    int b = bh >> 2, h = bh & 3;
    int rowbase = blockIdx.x * MT;
    int t = threadIdx.x, w = t >> 5, l = t & 31;
    int c = l & 3, r = l >> 2;

    const __half* WhTb = g_WhTH + ((size_t)bh*DH + dh*DHALF)*NNP;
    uint32_t whs_u32 = smem_u32(&Whs[0][0]);
    uint32_t lofs = 2u*((l & 7)*BPAD2 + (l >> 3)*8);

    // prologue: cp.async stage tile 0 (64 d-rows x 64 j = 512 16B chunks)
    #pragma unroll
    for (int i = 0; i < 2; i++){
        int chunk = t + 256*i;
        int row = chunk >> 3, seg = chunk & 7;
        CPA16(whs_u32 + row*(BPAD2*2) + seg*16,
              WhTb + (size_t)row*NNP + seg*8);
    }
    CPA_COMMIT();

    const float* f2b = g_f2 + bh*NN;
    float lm = -3.0e38f;
    #pragma unroll
    for (int i = 0; i < 8; i++){
        int idx = t + 256*i;
        float v = (idx < NN) ? f2b[idx]*LOG2E : 0.f;
        f2a[idx] = v;
        if (idx < NN) lm = fmaxf(lm, v);
    }
    #pragma unroll
    for (int off = 16; off; off >>= 1)
        lm = fmaxf(lm, __shfl_xor_sync(0xffffffffu, lm, off));
    if (l == 0) redm[w] = lm;
    CPA_WAIT0();
    __syncthreads();

    float M2L = redm[0];
    #pragma unroll
    for (int q = 1; q < 8; q++) M2L = fmaxf(M2L, redm[q]);

    int gr0 = rowbase + w*16 + r, gr1 = gr0 + 8;
    bool v0 = gr0 < NN, v1 = gr1 < NN;
    float c1_0 = 0.f, c2_0 = 0.f, c1_1 = 0.f, c2_1 = 0.f;
    int uf0 = 0, uf1 = 0;
    if (v0){
        float f1L = g_f1[bh*NN + gr0]*LOG2E;
        float tL = f1L + M2L, mL = fmaxf(tL, 0.2f*tL);
        c1_0 = f1L - mL; c2_0 = 0.2f*f1L - mL;
        uf0 = (g_hasnbr[gr0] == 0);
    }
    if (v1){
        float f1L = g_f1[bh*NN + gr1]*LOG2E;
        float tL = f1L + M2L, mL = fmaxf(tL, 0.2f*tL);
        c1_1 = f1L - mL; c2_1 = 0.2f*f1L - mL;
        uf1 = (g_hasnbr[gr1] == 0);
    }
    bool anyuf = __any_sync(0xffffffffu, (uf0 | uf1) != 0);

    unsigned long long c1p0 = packdup(c1_0), c2p0 = packdup(c2_0);
    unsigned long long c1p1 = packdup(c1_1), c2p1 = packdup(c2_1);
    unsigned long long k02  = packdup(0.2f);
    int shc = 2*c;

    float acc[8][4];
    #pragma unroll
    for (int nf = 0; nf < 8; nf++)
        #pragma unroll
        for (int q = 0; q < 4; q++) acc[nf][q] = 0.f;
    float accS[4] = {0.f, 0.f, 0.f, 0.f};

    for (int tile = 0; tile < NJT2; tile++){
        bool more = (tile + 1 < NJT2);
        int t32a = 2*tile, t32b = 2*tile + 1;
        unsigned awr[2][2];
        awr[0][0] = v0 ? g_adjT[t32a*2048 + gr0] : 0u;
        awr[0][1] = v1 ? g_adjT[t32a*2048 + gr1] : 0u;
        awr[1][0] = v0 ? g_adjT[t32b*2048 + gr0] : 0u;
        awr[1][1] = v1 ? g_adjT[t32b*2048 + gr1] : 0u;

        if (more){
            int j0n = (tile + 1)*JT2;
            uint32_t sb = whs_u32 + ((tile + 1) & 1)*(DHALF*BPAD2*2);
            #pragma unroll
            for (int i = 0; i < 2; i++){
                int chunk = t + 256*i;
                int row = chunk >> 3, seg = chunk & 7;
                CPA16(sb + row*(BPAD2*2) + seg*16,
                      WhTb + (size_t)row*NNP + j0n + seg*8);
            }
            CPA_COMMIT();
        }

        uint32_t cb = whs_u32 + (tile & 1)*(DHALF*BPAD2*2);
        #pragma unroll
        for (int sub = 0; sub < 2; sub++){
            int j0s = (2*tile + sub)*32;
            unsigned aw0 = awr[sub][0], aw1 = awr[sub][1];

            uint32_t u0  = (aw0 >> shc) << 6, u0b = u0 << 1;
            uint32_t u1  = (aw1 >> shc) << 6, u1b = u1 << 1;
            uint32_t m0A0 = prmtb(u0b, u0, 0xCC88), m0B0 = prmtb(u0b, u0, 0xDD99);
            uint32_t m0A1 = prmtb(u0b, u0, 0xEEAA), m0B1 = prmtb(u0b, u0, 0xFFBB);
            uint32_t m1A0 = prmtb(u1b, u1, 0xCC88), m1B0 = prmtb(u1b, u1, 0xDD99);
            uint32_t m1A1 = prmtb(u1b, u1, 0xEEAA), m1B1 = prmtb(u1b, u1, 0xFFBB);

            uint32_t afr[2][4];
            #pragma unroll
            for (int ks = 0; ks < 2; ks++){
                int j1 = 16*ks + shc;
                unsigned long long fpA = *(const unsigned long long*)&f2a[j0s + j1];
                unsigned long long fpB = *(const unsigned long long*)&f2a[j0s + j1 + 8];
                unsigned long long uA0 = add2(fpA, c1p0);
                unsigned long long tA0 = ffma2(fpA, k02, c2p0);
                unsigned long long uB0 = add2(fpB, c1p0);
                unsigned long long tB0 = ffma2(fpB, k02, c2p0);
                float a00 = fmaxf(u64lo(uA0), u64lo(tA0));
                float a01 = fmaxf(u64hi(uA0), u64hi(tA0));
                float a08 = fmaxf(u64lo(uB0), u64lo(tB0));
                float a09 = fmaxf(u64hi(uB0), u64hi(tB0));
                unsigned long long uA1 = add2(fpA, c1p1);
                unsigned long long tA1 = ffma2(fpA, k02, c2p1);
                unsigned long long uB1 = add2(fpB, c1p1);
                unsigned long long tB1 = ffma2(fpB, k02, c2p1);
                float b00 = fmaxf(u64lo(uA1), u64lo(tA1));
                float b01 = fmaxf(u64hi(uA1), u64hi(tA1));
                float b08 = fmaxf(u64lo(uB1), u64lo(tB1));
                float b09 = fmaxf(u64hi(uB1), u64hi(tB1));
                uint32_t p0A = ex2h2(packh2(a00, a01)) & (ks ? m0A1 : m0A0);
                uint32_t p1A = ex2h2(packh2(b00, b01)) & (ks ? m1A1 : m1A0);
                uint32_t p0B = ex2h2(packh2(a08, a09)) & (ks ? m0B1 : m0B0);
                uint32_t p1B = ex2h2(packh2(b08, b09)) & (ks ? m1B1 : m1B0);
                if (anyuf){
                    if (uf0){
                        uint32_t hA = ((j0s+j1   < NN) ? 0x3C00u : 0u)
                                    | ((j0s+j1+1 < NN) ? 0x3C000000u : 0u);
                        uint32_t hB = ((j0s+j1+8 < NN) ? 0x3C00u : 0u)
                                    | ((j0s+j1+9 < NN) ? 0x3C000000u : 0u);
                        p0A = hA; p0B = hB;
                    }
                    if (uf1){
                        uint32_t hA = ((j0s+j1   < NN) ? 0x3C00u : 0u)
                                    | ((j0s+j1+1 < NN) ? 0x3C000000u : 0u);
                        uint32_t hB = ((j0s+j1+8 < NN) ? 0x3C00u : 0u)
                                    | ((j0s+j1+9 < NN) ? 0x3C000000u : 0u);
                        p1A = hA; p1B = hB;
                    }
                }
                afr[ks][0] = p0A; afr[ks][1] = p1A;
                afr[ks][2] = p0B; afr[ks][3] = p1B;
            }

            mma_f16(accS, afr[0], ONES2, ONES2);
            mma_f16(accS, afr[1], ONES2, ONES2);

            uint32_t abase = cb + sub*64 + lofs;
            #pragma unroll
            for (int nf = 0; nf < 8; nf++){
                uint32_t b0, b1, b2, b3;
                ldsm_x4(b0, b1, b2, b3, abase + nf*(8*BPAD2*2));
                mma_f16(acc[nf], afr[0], b0, b1);
                mma_f16(acc[nf], afr[1], b2, b3);
            }
        }

        if (more) CPA_WAIT0();
        __syncthreads();
    }

    float r0inv = (v0 && accS[0] != 0.f) ? 1.0f/accS[0] : 0.f;
    float r1inv = (v1 && accS[2] != 0.f) ? 1.0f/accS[2] : 0.f;

    __half* hp0 = v0 ? &g_hpH[(((size_t)b*NN + gr0)*HH + h)*DH + dh*DHALF] : nullptr;
    __half* hp1 = v1 ? &g_hpH[(((size_t)b*NN + gr1)*HH + h)*DH + dh*DHALF] : nullptr;
    #pragma unroll
    for (int nf = 0; nf < 8; nf++){
        int d0 = 8*nf + 2*c;
        if (v0){
            float e0 = acc[nf][0]*r0inv; e0 = (e0 > 0.f) ? e0 : expm1f(e0);
            float e1 = acc[nf][1]*r0inv; e1 = (e1 > 0.f) ? e1 : expm1f(e1);
            *(uint32_t*)(hp0 + d0) = packh2(e0, e1);
        }
        if (v1){
            float e2 = acc[nf][2]*r1inv; e2 = (e2 > 0.f) ? e2 : expm1f(e2);
            float e3 = acc[nf][3]*r1inv; e3 = (e3 > 0.f) ? e3 : expm1f(e3);
            *(uint32_t*)(hp1 + d0) = packh2(e2, e3);
        }
    }
}

// ========== K4: g_enc = LN(elu(concat) @ Wp + bp) (cp.async double-buffer) ==
__global__ __launch_bounds__(256) void k_proj(const float* __restrict__ bp,
                                              const float* __restrict__ gamma,
                                              const float* __restrict__ beta){
    __shared__ __align__(16) __half As[2][DH*BPAD];
    __shared__ __align__(16) __half Bs[2][DH*BPAD];
    __shared__ float bps[DH], gms[DH], bts[DH];
    int nodebase = blockIdx.x * 128;
    int t = threadIdx.x, w = t >> 5, l = t & 31;
    int c = l & 3, r = l >> 2;
    int dq = t >> 1, seg = t & 1;

    if (t < DH){ bps[t] = bp[t]; gms[t] = gamma[t]; bts[t] = beta[t]; }

    float acc[16][4];
    #pragma unroll
    for (int nf = 0; nf < 16; nf++)
        #pragma unroll
        for (int q = 0; q < 4; q++) acc[nf][q] = 0.f;

    const __half* Ab = g_hpH + (size_t)nodebase*512;
    uint32_t as0 = smem_u32(&As[0][0]);
    uint32_t bs0 = smem_u32(&Bs[0][0]);
    const int BUFB = DH*BPAD*2;
    uint32_t sofs = 2u*(dq*BPAD + seg*16);

    {
        const __half* ga = Ab + (size_t)dq*512 + seg*16;
        const __half* gb = g_WpTH + dq*WPK + seg*16;
        CPA16(as0 + sofs, ga); CPA16(as0 + sofs + 16, ga + 8);
        CPA16(bs0 + sofs, gb); CPA16(bs0 + sofs + 16, gb + 8);
        CPA_COMMIT();
    }

    for (int kc = 0; kc < 16; kc++){
        CPA_WAIT0();
        __syncthreads();
        if (kc + 1 < 16){
            int nb = (kc + 1) & 1;
            const __half* ga = Ab + (size_t)dq*512 + (kc+1)*32 + seg*16;
            const __half* gb = g_WpTH + dq*WPK + (kc+1)*32 + seg*16;
            CPA16(as0 + nb*BUFB + sofs, ga); CPA16(as0 + nb*BUFB + sofs + 16, ga + 8);
            CPA16(bs0 + nb*BUFB + sofs, gb); CPA16(bs0 + nb*BUFB + sofs + 16, gb + 8);
            CPA_COMMIT();
        }
        const __half* Ac = As[kc & 1];
        const __half* Bc = Bs[kc & 1];

        #pragma unroll
        for (int ks = 0; ks < 2; ks++){
            uint32_t af[4];
            af[0] = *(const uint32_t*)&Ac[(w*16 + r    )*BPAD + 16*ks + 2*c];
            af[1] = *(const uint32_t*)&Ac[(w*16 + r + 8)*BPAD + 16*ks + 2*c];
            af[2] = *(const uint32_t*)&Ac[(w*16 + r    )*BPAD + 16*ks + 2*c + 8];
            af[3] = *(const uint32_t*)&Ac[(w*16 + r + 8)*BPAD + 16*ks + 2*c + 8];
            #pragma unroll
            for (int nf = 0; nf < 16; nf++){
                const __half* bpp = &Bc[(8*nf + r)*BPAD + 16*ks + 2*c];
                mma_f16(acc[nf], af, *(const uint32_t*)bpp, *(const uint32_t*)(bpp + 8));
            }
        }
    }

    float s0 = 0.f, q0 = 0.f, s1 = 0.f, q1 = 0.f;
    #pragma unroll
    for (int nf = 0; nf < 16; nf++){
        int d0 = 8*nf + 2*c;
        float a0 = acc[nf][0] + bps[d0],   a1v = acc[nf][1] + bps[d0+1];
        float a2 = acc[nf][2] + bps[d0],   a3v = acc[nf][3] + bps[d0+1];
        s0 += a0 + a1v;  q0 += a0*a0 + a1v*a1v;
        s1 += a2 + a3v;  q1 += a2*a2 + a3v*a3v;
    }
    #pragma unroll
    for (int off = 1; off <= 2; off <<= 1){
        s0 += __shfl_xor_sync(0xffffffffu, s0, off);
        q0 += __shfl_xor_sync(0xffffffffu, q0, off);
        s1 += __shfl_xor_sync(0xffffffffu, s1, off);
        q1 += __shfl_xor_sync(0xffffffffu, q1, off);
    }
    float m0 = s0*(1.0f/DH), var0 = q0*(1.0f/DH) - m0*m0;
    float m1 = s1*(1.0f/DH), var1 = q1*(1.0f/DH) - m1*m1;
    float rs0 = rsqrtf(var0 + LN_EPS), rs1 = rsqrtf(var1 + LN_EPS);

    int n0 = nodebase + w*16 + r, n1 = n0 + 8;
    #pragma unroll
    for (int nf = 0; nf < 16; nf++){
        int d0 = 8*nf + 2*c;
        float g0v = gms[d0], g1v = gms[d0+1], t0v = bts[d0], t1v = bts[d0+1];
        float a0 = acc[nf][0] + bps[d0],   a1v = acc[nf][1] + bps[d0+1];
        float a2 = acc[nf][2] + bps[d0],   a3v = acc[nf][3] + bps[d0+1];
        *(float2*)&g_enc[(size_t)n0*DH + d0] =
            make_float2((a0 - m0)*rs0*g0v + t0v, (a1v - m0)*rs0*g1v + t1v);
        *(float2*)&g_enc[(size_t)n1*DH + d0] =
            make_float2((a2 - m1)*rs1*g0v + t0v, (a3v - m1)*rs1*g1v + t1v);
    }
}

// ================= K5a: pooling partials (128 CTAs — parallel) ==============
__global__ __launch_bounds__(256) void k_pool(){
    int chunk = blockIdx.x, b = blockIdx.y;
    int t = threadIdx.x, d = t & 127, g2 = t >> 7;
    const float* eb = g_enc + (size_t)b*NN*DH;
    int n0 = chunk*125;
    float s = 0.f;
    for (int n = n0 + g2; n < n0 + 125; n += 2)
        s += eb[(size_t)n*DH + d];
    __shared__ float sh[128];
    if (g2 == 0) sh[d] = s;
    __syncthreads();
    if (g2 == 1) g_part[(b*16 + chunk)*DH + d] = sh[d] + s;
}

// ================= K5b: route emb + MLP head ================================
__global__ __launch_bounds__(256) void k_head2(const int* __restrict__ routes_raw,
        const float* __restrict__ W1, const float* __restrict__ b1,
        const float* __restrict__ W2, const float* __restrict__ b2,
        const float* __restrict__ Wv1, const float* __restrict__ bv1,
        const float* __restrict__ Wv2, const float* __restrict__ bv2,
        float* __restrict__ out){
    __shared__ float ge[DH], re[DH], comb[2*DH], h1[DH], h2[64], h3[32];
    __shared__ int ridx[RL];
    __shared__ float rvalid[RL];
    __shared__ unsigned notseen64;
    __shared__ float cnt_s;

    int b = blockIdx.x;
    int t = threadIdx.x;

    if (t == 0) notseen64 = 0u;
    __syncthreads();
    if (t < 200){
        int hi = routes_raw[2*t + 1];
        if (hi != 0 && hi != -1) atomicOr(&notseen64, 1u);
    }
    __syncthreads();
    int is64 = (notseen64 == 0u);
    if (t < RL){
        long long v;
        if (is64) v = ((const long long*)routes_raw)[b*RL + t];
        else      v = (long long)routes_raw[b*RL + t];
        ridx[t]   = (v < 0) ? 0 : (int)v;
        rvalid[t] = (v >= 0) ? 1.f : 0.f;
    }
    __syncthreads();

    int d = t & 127, g2 = t >> 7;
    const float* eb = g_enc + (size_t)b*NN*DH;
    float ga = 0.f;
    for (int cch = g2*8; cch < g2*8 + 8; cch++)
        ga += g_part[(b*16 + cch)*DH + d];
    float ra = 0.f;
    for (int lr = g2; lr < RL; lr += 2)
        ra += rvalid[lr] * eb[(size_t)ridx[lr]*DH + d];
    if (g2 == 0){ ge[d] = ga; re[d] = ra; }
    __syncthreads();
    if (g2 == 1){ ge[d] += ga; re[d] += ra; }
    if (t == 0){
        float cc = 0.f;
        for (int lr = 0; lr < RL; lr++) cc += rvalid[lr];
        cnt_s = cc;
    }
    __syncthreads();
    if (t < DH)        comb[t] = (cnt_s > 0.f) ? re[t] / fmaxf(cnt_s, 1.f) : 0.f;
    else if (t < 2*DH) comb[t] = ge[t - DH] * (1.0f/NN);
    __syncthreads();

    if (t < DH){
        float a = b1[t];
        for (int k = 0; k < 2*DH; k++) a = fmaf(comb[k], W1[k*DH + t], a);
        h1[t] = fmaxf(a, 0.f);
    }
    __syncthreads();
    if (t < 64){
        float a = b2[t];
        for (int k = 0; k < DH; k++) a = fmaf(h1[k], W2[k*64 + t], a);
        h2[t] = fmaxf(a, 0.f);
    }
    __syncthreads();
    if (t < 32){
        float a = bv1[t];
        for (int k = 0; k < 64; k++) a = fmaf(h2[k], Wv1[k*32 + t], a);
        h3[t] = fmaxf(a, 0.f);
    }
    __syncthreads();
    if (t < 3){
        float a = bv2[t];
        for (int k = 0; k < 32; k++) a = fmaf(h3[k], Wv2[k*3 + t], a);
        out[b*3 + t] = a;
    }
}

// ================= launch ===================================================
extern "C" void kernel_launch(void* const* d_in, const int* in_sizes, int n_in,
                              void* d_out, int out_size){
    (void)in_sizes; (void)n_in; (void)out_size;
    const float* nf     = (const float*)d_in[0];
    const int*   routes = (const int*)  d_in[1];
    const int*   adj    = (const int*)  d_in[2];
    const float* Wheads = (const float*)d_in[3];
    const float* a1     = (const float*)d_in[4];
    const float* a2     = (const float*)d_in[5];
    const float* Wp     = (const float*)d_in[6];
    const float* bp     = (const float*)d_in[7];
    const float* gamma  = (const float*)d_in[8];
    const float* beta   = (const float*)d_in[9];
    const float* W1     = (const float*)d_in[10];
    const float* b1     = (const float*)d_in[11];
    const float* W2     = (const float*)d_in[12];
    const float* b2     = (const float*)d_in[13];
    const float* Wv1    = (const float*)d_in[14];
    const float* bv1    = (const float*)d_in[15];
    const float* Wv2    = (const float*)d_in[16];
    const float* bv2    = (const float*)d_in[17];
    float* out = (float*)d_out;

    k_pack <<<NN, 256>>>(adj);
    k_wh   <<<dim3(63, BH), 256>>>(nf, Wheads, a1, a2);
    k_wpcvt<<<256, 256>>>(Wp);                     // keeps k_attn at profiled slot
    k_attn <<<dim3(NMT, BH*2), 256>>>();           // d-split: 1024 CTAs
    k_proj <<<125, 256>>>(bp, gamma, beta);
    k_pool <<<dim3(16, BB), 256>>>();
    k_head2<<<BB, 256>>>(routes, W1, b1, W2, b2, Wv1, bv1, Wv2, bv2, out);
}

// round 16
// speedup vs baseline: 1.0706x; 1.0706x over previous
#include <cuda_runtime.h>
#include <cuda_fp16.h>
#include <cstdint>
#include <math.h>

#define NN   2000
#define NNP  2048      // padded j-dim for WhT (covers 32 tiles of 64)
#define BB   8
#define HH   4
#define DIN  64
#define DH   128
#define BH   32        // BB*HH
#define RL   50
#define MT   128       // attention M tile (rows per CTA)
#define NMT  16        // ceil(2000/128)
#define JT2  64        // attention j tile
#define NJT2 32        // 2048/64
#define LOG2E 1.4426950408889634f
#define LN_EPS 1e-5f
#define BPAD 40        // k_proj smem row stride in halves
#define BPAD2 72       // k_attn smem tile row stride in halves (64 + 8 pad)
#define WPK  520       // WpT row stride in halves (512 + 8 pad)
#define ONES2 0x3C003C00u   // two f16 1.0

// ---------------- device scratch (static; zero-initialized at load) ---------
__device__ __half   g_WhTH[(size_t)BH*DH*NNP];   // [(bh*128+d)][j] transposed Wh, f16
__device__ float    g_f1 [BH*NN];
__device__ float    g_f2 [BH*NN];
__device__ unsigned g_adjT[64*2048];             // [tile32][row] packed adjacency
__device__ int      g_hasnbr[NN];
__device__ __half   g_hpH[(size_t)BB*NN*HH*DH];  // elu(h_prime) node-major, f16
__device__ __half   g_WpTH[DH*WPK];              // WpT [n][k] f16
__device__ float    g_enc[(size_t)BB*NN*DH];
__device__ float    g_part[BB*16*DH];            // pooling partials

// ---------------- helpers ----------------------------------------------------
__device__ __forceinline__ uint32_t packh2(float lo, float hi){
    __half2 h = __floats2half2_rn(lo, hi);
    return *reinterpret_cast<uint32_t*>(&h);
}
__device__ __forceinline__ float ex2f(float x){
    float r; asm("ex2.approx.ftz.f32 %0, %1;" : "=f"(r) : "f"(x)); return r;
}
__device__ __forceinline__ uint32_t ex2h2(uint32_t a){
    uint32_t r; asm("ex2.approx.f16x2 %0, %1;" : "=r"(r) : "r"(a)); return r;
}
__device__ __forceinline__ uint32_t prmtb(uint32_t a, uint32_t b, uint32_t s){
    uint32_t d; asm("prmt.b32 %0, %1, %2, %3;" : "=r"(d) : "r"(a), "r"(b), "r"(s));
    return d;
}
__device__ __forceinline__ uint32_t smem_u32(const void* p){
    uint32_t a;
    asm("{ .reg .u64 t; cvta.to.shared.u64 t, %1; cvt.u32.u64 %0, t; }"
        : "=r"(a) : "l"(p));
    return a;
}
// packed f32x2 (lanewise IEEE-identical to scalar add/fma)
__device__ __forceinline__ unsigned long long add2(unsigned long long a,
                                                   unsigned long long b){
    unsigned long long d;
    asm("add.rn.f32x2 %0, %1, %2;" : "=l"(d) : "l"(a), "l"(b));
    return d;
}
__device__ __forceinline__ unsigned long long ffma2(unsigned long long a,
                                                    unsigned long long b,
                                                    unsigned long long c){
    unsigned long long d;
    asm("fma.rn.f32x2 %0, %1, %2, %3;" : "=l"(d) : "l"(a), "l"(b), "l"(c));
    return d;
}
__device__ __forceinline__ unsigned long long packdup(float p){
    unsigned long long d;
    asm("mov.b64 %0, {%1, %2};" : "=l"(d) : "f"(p), "f"(p));
    return d;
}
__device__ __forceinline__ float u64lo(unsigned long long v){
    return __uint_as_float((unsigned)(v & 0xffffffffULL));
}
__device__ __forceinline__ float u64hi(unsigned long long v){
    return __uint_as_float((unsigned)(v >> 32));
}
__device__ __forceinline__ void mma_f16(float* c, const uint32_t* a,
                                        uint32_t b0, uint32_t b1){
    asm volatile("mma.sync.aligned.m16n8k16.row.col.f32.f16.f16.f32 "
        "{%0,%1,%2,%3}, {%4,%5,%6,%7}, {%8,%9}, {%0,%1,%2,%3};"
        : "+f"(c[0]), "+f"(c[1]), "+f"(c[2]), "+f"(c[3])
        : "r"(a[0]), "r"(a[1]), "r"(a[2]), "r"(a[3]), "r"(b0), "r"(b1));
}
__device__ __forceinline__ void ldsm_x4(uint32_t& r0, uint32_t& r1,
                                        uint32_t& r2, uint32_t& r3, uint32_t a){
    asm volatile("ldmatrix.sync.aligned.m8n8.x4.shared.b16 {%0,%1,%2,%3}, [%4];"
        : "=r"(r0), "=r"(r1), "=r"(r2), "=r"(r3) : "r"(a));
}
#define CPA16(s,g)   asm volatile("cp.async.cg.shared.global [%0], [%1], 16;" :: "r"(s), "l"(g))
#define CPA_COMMIT() asm volatile("cp.async.commit_group;" ::: "memory")
#define CPA_WAIT0()  asm volatile("cp.async.wait_group 0;" ::: "memory")

// ==== K0: pack adjacency (transposed) — int4 loads + shfl-OR assembly =======
__global__ __launch_bounds__(256) void k_pack(const int* __restrict__ adj){
    int i = blockIdx.x;
    int t = threadIdx.x;
    int w = t >> 5, l = t & 31;
    __shared__ unsigned orr;
    if (t == 0) orr = 0u;
    __syncthreads();

    const int* rowp = adj + (size_t)i*NN;
    unsigned wor = 0u;
    #pragma unroll
    for (int pass = 0; pass < 2; pass++){
        int j = pass*1024 + w*128 + l*4;
        unsigned nib = 0u;
        if (j < NN){   // j multiple of 4; j<=1996 -> int4 in-bounds
            int4 v4 = *(const int4*)(rowp + j);
            nib  = (v4.x > 0) ? 1u : 0u;
            nib |= (v4.y > 0) ? 2u : 0u;
            nib |= (v4.z > 0) ? 4u : 0u;
            nib |= (v4.w > 0) ? 8u : 0u;
        }
        unsigned v = nib << ((l & 7)*4);
        v |= __shfl_xor_sync(0xffffffffu, v, 1);
        v |= __shfl_xor_sync(0xffffffffu, v, 2);
        v |= __shfl_xor_sync(0xffffffffu, v, 4);
        if ((l & 7) == 0){
            int g = pass*32 + w*4 + (l >> 3);
            g_adjT[g*2048 + i] = v;
            wor |= v;
        }
    }
    if ((l & 7) == 0 && wor) atomicOr(&orr, 1u);
    __syncthreads();
    if (t == 0) g_hasnbr[i] = (orr != 0u);
}

// ================= K1: WhT = (X @ W_heads)^T (f16)  (+ f1, f2) ==============
__global__ __launch_bounds__(256) void k_wh(const float* __restrict__ nf,
                                            const float* __restrict__ Wheads,
                                            const float* __restrict__ a1,
                                            const float* __restrict__ a2){
    __shared__ __align__(16) float Ws[DIN*DH];
    __shared__ float Xs[32][DIN+1];
    __shared__ float a1s[DH], a2s[DH];
    __shared__ float f1p[32][17], f2p[32][17];

    int bh = blockIdx.y;
    int t = threadIdx.x;
    int h  = bh & 3, b = bh >> 2;
    int rowbase = blockIdx.x * 32;

    const float* Wg = Wheads + (size_t)h*DIN*DH;
    for (int i = t; i < DIN*DH; i += 256) Ws[i] = Wg[i];
    if (t < DH){ a1s[t] = a1[h*DH+t]; a2s[t] = a2[h*DH+t]; }
    for (int i = t; i < 32*DIN; i += 256){
        int r = i >> 6, d = i & 63;
        int row = rowbase + r;
        Xs[r][d] = (row < NN) ? nf[((size_t)b*NN + row)*DIN + d] : 0.f;
    }
    __syncthreads();

    int tr = t >> 4, tc = t & 15;
    int r0 = tr*2, c0 = tc*8;
    unsigned long long acc2[2][4];
    #pragma unroll
    for (int r = 0; r < 2; r++)
        #pragma unroll
        for (int cc = 0; cc < 4; cc++) acc2[r][cc] = 0ull;

    #pragma unroll 4
    for (int k = 0; k < DIN; k++){
        unsigned long long x0p = packdup(Xs[r0][k]);
        unsigned long long x1p = packdup(Xs[r0+1][k]);
        const unsigned long long* wrow =
            (const unsigned long long*)&Ws[k*DH + c0];
        #pragma unroll
        for (int cc = 0; cc < 4; cc++){
            unsigned long long wp = wrow[cc];
            acc2[0][cc] = ffma2(x0p, wp, acc2[0][cc]);
            acc2[1][cc] = ffma2(x1p, wp, acc2[1][cc]);
        }
    }
    float acc[2][8];
    #pragma unroll
    for (int r = 0; r < 2; r++)
        #pragma unroll
        for (int cc = 0; cc < 4; cc++){
            acc[r][2*cc]   = u64lo(acc2[r][cc]);
            acc[r][2*cc+1] = u64hi(acc2[r][cc]);
        }

    #pragma unroll
    for (int r = 0; r < 2; r++){
        float p1 = 0.f, p2 = 0.f;
        #pragma unroll
        for (int c = 0; c < 8; c++){
            p1 = fmaf(acc[r][c], a1s[c0+c], p1);
            p2 = fmaf(acc[r][c], a2s[c0+c], p2);
        }
        f1p[r0+r][tc] = p1;
        f2p[r0+r][tc] = p2;
    }
    __syncthreads();
    if (t < 32){
        float s1 = 0.f, s2 = 0.f;
        #pragma unroll
        for (int c = 0; c < 16; c++){ s1 += f1p[t][c]; s2 += f2p[t][c]; }
        int row = rowbase + t;
        if (row < NN){ g_f1[bh*NN+row] = s1; g_f2[bh*NN+row] = s2; }
    }
    float* Ts = Ws;   // [d][r] padded: d*33 + r
    #pragma unroll
    for (int r = 0; r < 2; r++)
        #pragma unroll
        for (int c = 0; c < 8; c++)
            Ts[(c0+c)*33 + (r0+r)] = acc[r][c];
    __syncthreads();
    {
        int d = t >> 1, hf = t & 1;
        int colbase = rowbase + hf*16;
        const float* src = &Ts[d*33 + hf*16];
        __half* dst = &g_WhTH[((size_t)bh*DH + d)*NNP + colbase];
        if (colbase + 16 <= NN){
            uint32_t u[8];
            #pragma unroll
            for (int q = 0; q < 8; q++) u[q] = packh2(src[2*q], src[2*q+1]);
            *(uint4*)dst       = make_uint4(u[0],u[1],u[2],u[3]);
            *(uint4*)(dst + 8) = make_uint4(u[4],u[5],u[6],u[7]);
        } else {
            for (int i = 0; i < 16; i++)
                if (colbase + i < NN) dst[i] = __float2half_rn(src[i]);
        }
    }
}

// ================= K2: WpT f16 conversion (keeps k_attn at profiled slot) ===
__global__ __launch_bounds__(256) void k_wpcvt(const float* __restrict__ Wp){
    int id = blockIdx.x*256 + threadIdx.x;
    if (id < 512*128){
        int k = id >> 7, n = id & 127;
        g_WpTH[n*WPK + k] = __float2half_rn(Wp[id]);
    }
}

// ====== K3: fused attention via mma.sync f16 (R12 mainloop, elu via ex2) ====
__global__ __launch_bounds__(256,2) void k_attn(){
    __shared__ __align__(16) float  f2a[NNP];
    __shared__ __align__(16) __half Whs[2][DH*BPAD2];   // 2 x 18432 B
    __shared__ float  redm[8];

    int bh = blockIdx.y;
    int b = bh >> 2, h = bh & 3;
    int rowbase = blockIdx.x * MT;
    int t = threadIdx.x, w = t >> 5, l = t & 31;
    int c = l & 3, r = l >> 2;

    const __half* WhTb = g_WhTH + (size_t)bh*DH*NNP;
    uint32_t whs_u32 = smem_u32(&Whs[0][0]);
    uint32_t lofs = 2u*((l & 7)*BPAD2 + (l >> 3)*8);

    #pragma unroll
    for (int i = 0; i < 4; i++){
        int chunk = t + 256*i;
        int row = chunk >> 3, seg = chunk & 7;
        CPA16(whs_u32 + row*(BPAD2*2) + seg*16,
              WhTb + (size_t)row*NNP + seg*8);
    }
    CPA_COMMIT();

    const float* f2b = g_f2 + bh*NN;
    float lm = -3.0e38f;
    #pragma unroll
    for (int i = 0; i < 8; i++){
        int idx = t + 256*i;
        float v = (idx < NN) ? f2b[idx]*LOG2E : 0.f;
        f2a[idx] = v;
        if (idx < NN) lm = fmaxf(lm, v);
    }
    #pragma unroll
    for (int off = 16; off; off >>= 1)
        lm = fmaxf(lm, __shfl_xor_sync(0xffffffffu, lm, off));
    if (l == 0) redm[w] = lm;
    CPA_WAIT0();
    __syncthreads();

    float M2L = redm[0];
    #pragma unroll
    for (int q = 1; q < 8; q++) M2L = fmaxf(M2L, redm[q]);

    int gr0 = rowbase + w*16 + r, gr1 = gr0 + 8;
    bool v0 = gr0 < NN, v1 = gr1 < NN;
    float c1_0 = 0.f, c2_0 = 0.f, c1_1 = 0.f, c2_1 = 0.f;
    int uf0 = 0, uf1 = 0;
    if (v0){
        float f1L = g_f1[bh*NN + gr0]*LOG2E;
        float tL = f1L + M2L, mL = fmaxf(tL, 0.2f*tL);
        c1_0 = f1L - mL; c2_0 = 0.2f*f1L - mL;
        uf0 = (g_hasnbr[gr0] == 0);
    }
    if (v1){
        float f1L = g_f1[bh*NN + gr1]*LOG2E;
        float tL = f1L + M2L, mL = fmaxf(tL, 0.2f*tL);
        c1_1 = f1L - mL; c2_1 = 0.2f*f1L - mL;
        uf1 = (g_hasnbr[gr1] == 0);
    }
    bool anyuf = __any_sync(0xffffffffu, (uf0 | uf1) != 0);

    unsigned long long c1p0 = packdup(c1_0), c2p0 = packdup(c2_0);
    unsigned long long c1p1 = packdup(c1_1), c2p1 = packdup(c2_1);
    unsigned long long k02  = packdup(0.2f);
    int shc = 2*c;

    float acc[16][4];
    #pragma unroll
    for (int nf = 0; nf < 16; nf++)
        #pragma unroll
        for (int q = 0; q < 4; q++) acc[nf][q] = 0.f;
    float accS[4] = {0.f, 0.f, 0.f, 0.f};

    for (int tile = 0; tile < NJT2; tile++){
        bool more = (tile + 1 < NJT2);
        int t32a = 2*tile, t32b = 2*tile + 1;
        unsigned awr[2][2];
        awr[0][0] = v0 ? g_adjT[t32a*2048 + gr0] : 0u;
        awr[0][1] = v1 ? g_adjT[t32a*2048 + gr1] : 0u;
        awr[1][0] = v0 ? g_adjT[t32b*2048 + gr0] : 0u;
        awr[1][1] = v1 ? g_adjT[t32b*2048 + gr1] : 0u;

        if (more){
            int j0n = (tile + 1)*JT2;
            uint32_t sb = whs_u32 + ((tile + 1) & 1)*(DH*BPAD2*2);
            #pragma unroll
            for (int i = 0; i < 4; i++){
                int chunk = t + 256*i;
                int row = chunk >> 3, seg = chunk & 7;
                CPA16(sb + row*(BPAD2*2) + seg*16,
                      WhTb + (size_t)row*NNP + j0n + seg*8);
            }
            CPA_COMMIT();
        }

        uint32_t cb = whs_u32 + (tile & 1)*(DH*BPAD2*2);
        #pragma unroll
        for (int sub = 0; sub < 2; sub++){
            int j0s = (2*tile + sub)*32;
            unsigned aw0 = awr[sub][0], aw1 = awr[sub][1];

            uint32_t u0  = (aw0 >> shc) << 6, u0b = u0 << 1;
            uint32_t u1  = (aw1 >> shc) << 6, u1b = u1 << 1;
            uint32_t m0A0 = prmtb(u0b, u0, 0xCC88), m0B0 = prmtb(u0b, u0, 0xDD99);
            uint32_t m0A1 = prmtb(u0b, u0, 0xEEAA), m0B1 = prmtb(u0b, u0, 0xFFBB);
            uint32_t m1A0 = prmtb(u1b, u1, 0xCC88), m1B0 = prmtb(u1b, u1, 0xDD99);
            uint32_t m1A1 = prmtb(u1b, u1, 0xEEAA), m1B1 = prmtb(u1b, u1, 0xFFBB);

            uint32_t afr[2][4];
            #pragma unroll
            for (int ks = 0; ks < 2; ks++){
                int j1 = 16*ks + shc;
                unsigned long long fpA = *(const unsigned long long*)&f2a[j0s + j1];
                unsigned long long fpB = *(const unsigned long long*)&f2a[j0s + j1 + 8];
                unsigned long long uA0 = add2(fpA, c1p0);
                unsigned long long tA0 = ffma2(fpA, k02, c2p0);
                unsigned long long uB0 = add2(fpB, c1p0);
                unsigned long long tB0 = ffma2(fpB, k02, c2p0);
                float a00 = fmaxf(u64lo(uA0), u64lo(tA0));
                float a01 = fmaxf(u64hi(uA0), u64hi(tA0));
                float a08 = fmaxf(u64lo(uB0), u64lo(tB0));
                float a09 = fmaxf(u64hi(uB0), u64hi(tB0));
                unsigned long long uA1 = add2(fpA, c1p1);
                unsigned long long tA1 = ffma2(fpA, k02, c2p1);
                unsigned long long uB1 = add2(fpB, c1p1);
                unsigned long long tB1 = ffma2(fpB, k02, c2p1);
                float b00 = fmaxf(u64lo(uA1), u64lo(tA1));
                float b01 = fmaxf(u64hi(uA1), u64hi(tA1));
                float b08 = fmaxf(u64lo(uB1), u64lo(tB1));
                float b09 = fmaxf(u64hi(uB1), u64hi(tB1));
                uint32_t p0A = ex2h2(packh2(a00, a01)) & (ks ? m0A1 : m0A0);
                uint32_t p1A = ex2h2(packh2(b00, b01)) & (ks ? m1A1 : m1A0);
                uint32_t p0B = ex2h2(packh2(a08, a09)) & (ks ? m0B1 : m0B0);
                uint32_t p1B = ex2h2(packh2(b08, b09)) & (ks ? m1B1 : m1B0);
                if (anyuf){
                    if (uf0){
                        uint32_t hA = ((j0s+j1   < NN) ? 0x3C00u : 0u)
                                    | ((j0s+j1+1 < NN) ? 0x3C000000u : 0u);
                        uint32_t hB = ((j0s+j1+8 < NN) ? 0x3C00u : 0u)
                                    | ((j0s+j1+9 < NN) ? 0x3C000000u : 0u);
                        p0A = hA; p0B = hB;
                    }
                    if (uf1){
                        uint32_t hA = ((j0s+j1   < NN) ? 0x3C00u : 0u)
                                    | ((j0s+j1+1 < NN) ? 0x3C000000u : 0u);
                        uint32_t hB = ((j0s+j1+8 < NN) ? 0x3C00u : 0u)
                                    | ((j0s+j1+9 < NN) ? 0x3C000000u : 0u);
                        p1A = hA; p1B = hB;
                    }
                }
                afr[ks][0] = p0A; afr[ks][1] = p1A;
                afr[ks][2] = p0B; afr[ks][3] = p1B;
            }

            mma_f16(accS, afr[0], ONES2, ONES2);
            mma_f16(accS, afr[1], ONES2, ONES2);

            uint32_t abase = cb + sub*64 + lofs;
            #pragma unroll
            for (int nf = 0; nf < 16; nf++){
                uint32_t b0, b1, b2, b3;
                ldsm_x4(b0, b1, b2, b3, abase + nf*(8*BPAD2*2));
                mma_f16(acc[nf], afr[0], b0, b1);
                mma_f16(acc[nf], afr[1], b2, b3);
            }
        }

        if (more) CPA_WAIT0();
        __syncthreads();
    }

    float r0inv = (v0 && accS[0] != 0.f) ? 1.0f/accS[0] : 0.f;
    float r1inv = (v1 && accS[2] != 0.f) ? 1.0f/accS[2] : 0.f;

    __half* hp0 = v0 ? &g_hpH[(((size_t)b*NN + gr0)*HH + h)*DH] : nullptr;
    __half* hp1 = v1 ? &g_hpH[(((size_t)b*NN + gr1)*HH + h)*DH] : nullptr;
    #pragma unroll
    for (int nf = 0; nf < 16; nf++){
        int d0 = 8*nf + 2*c;
        if (v0){
            float e0 = acc[nf][0]*r0inv;
            e0 = (e0 > 0.f) ? e0 : ex2f(e0*LOG2E) - 1.0f;
            float e1 = acc[nf][1]*r0inv;
            e1 = (e1 > 0.f) ? e1 : ex2f(e1*LOG2E) - 1.0f;
            *(uint32_t*)(hp0 + d0) = packh2(e0, e1);
        }
        if (v1){
            float e2 = acc[nf][2]*r1inv;
            e2 = (e2 > 0.f) ? e2 : ex2f(e2*LOG2E) - 1.0f;
            float e3 = acc[nf][3]*r1inv;
            e3 = (e3 > 0.f) ? e3 : ex2f(e3*LOG2E) - 1.0f;
            *(uint32_t*)(hp1 + d0) = packh2(e2, e3);
        }
    }
}

// ========== K4: g_enc = LN(elu(concat) @ Wp + bp) (cp.async double-buffer) ==
__global__ __launch_bounds__(256) void k_proj(const float* __restrict__ bp,
                                              const float* __restrict__ gamma,
                                              const float* __restrict__ beta){
    __shared__ __align__(16) __half As[2][DH*BPAD];
    __shared__ __align__(16) __half Bs[2][DH*BPAD];
    __shared__ float bps[DH], gms[DH], bts[DH];
    int nodebase = blockIdx.x * 128;
    int t = threadIdx.x, w = t >> 5, l = t & 31;
    int c = l & 3, r = l >> 2;
    int dq = t >> 1, seg = t & 1;

    if (t < DH){ bps[t] = bp[t]; gms[t] = gamma[t]; bts[t] = beta[t]; }

    float acc[16][4];
    #pragma unroll
    for (int nf = 0; nf < 16; nf++)
        #pragma unroll
        for (int q = 0; q < 4; q++) acc[nf][q] = 0.f;

    const __half* Ab = g_hpH + (size_t)nodebase*512;
    uint32_t as0 = smem_u32(&As[0][0]);
    uint32_t bs0 = smem_u32(&Bs[0][0]);
    const int BUFB = DH*BPAD*2;
    uint32_t sofs = 2u*(dq*BPAD + seg*16);

    {
        const __half* ga = Ab + (size_t)dq*512 + seg*16;
        const __half* gb = g_WpTH + dq*WPK + seg*16;
        CPA16(as0 + sofs, ga); CPA16(as0 + sofs + 16, ga + 8);
        CPA16(bs0 + sofs, gb); CPA16(bs0 + sofs + 16, gb + 8);
        CPA_COMMIT();
    }

    for (int kc = 0; kc < 16; kc++){
        CPA_WAIT0();
        __syncthreads();
        if (kc + 1 < 16){
            int nb = (kc + 1) & 1;
            const __half* ga = Ab + (size_t)dq*512 + (kc+1)*32 + seg*16;
            const __half* gb = g_WpTH + dq*WPK + (kc+1)*32 + seg*16;
            CPA16(as0 + nb*BUFB + sofs, ga); CPA16(as0 + nb*BUFB + sofs + 16, ga + 8);
            CPA16(bs0 + nb*BUFB + sofs, gb); CPA16(bs0 + nb*BUFB + sofs + 16, gb + 8);
            CPA_COMMIT();
        }
        const __half* Ac = As[kc & 1];
        const __half* Bc = Bs[kc & 1];

        #pragma unroll
        for (int ks = 0; ks < 2; ks++){
            uint32_t af[4];
            af[0] = *(const uint32_t*)&Ac[(w*16 + r    )*BPAD + 16*ks + 2*c];
            af[1] = *(const uint32_t*)&Ac[(w*16 + r + 8)*BPAD + 16*ks + 2*c];
            af[2] = *(const uint32_t*)&Ac[(w*16 + r    )*BPAD + 16*ks + 2*c + 8];
            af[3] = *(const uint32_t*)&Ac[(w*16 + r + 8)*BPAD + 16*ks + 2*c + 8];
            #pragma unroll
            for (int nf = 0; nf < 16; nf++){
                const __half* bpp = &Bc[(8*nf + r)*BPAD + 16*ks + 2*c];
                mma_f16(acc[nf], af, *(const uint32_t*)bpp, *(const uint32_t*)(bpp + 8));
            }
        }
    }

    float s0 = 0.f, q0 = 0.f, s1 = 0.f, q1 = 0.f;
    #pragma unroll
    for (int nf = 0; nf < 16; nf++){
        int d0 = 8*nf + 2*c;
        float a0 = acc[nf][0] + bps[d0],   a1v = acc[nf][1] + bps[d0+1];
        float a2 = acc[nf][2] + bps[d0],   a3v = acc[nf][3] + bps[d0+1];
        s0 += a0 + a1v;  q0 += a0*a0 + a1v*a1v;
        s1 += a2 + a3v;  q1 += a2*a2 + a3v*a3v;
    }
    #pragma unroll
    for (int off = 1; off <= 2; off <<= 1){
        s0 += __shfl_xor_sync(0xffffffffu, s0, off);
        q0 += __shfl_xor_sync(0xffffffffu, q0, off);
        s1 += __shfl_xor_sync(0xffffffffu, s1, off);
        q1 += __shfl_xor_sync(0xffffffffu, q1, off);
    }
    float m0 = s0*(1.0f/DH), var0 = q0*(1.0f/DH) - m0*m0;
    float m1 = s1*(1.0f/DH), var1 = q1*(1.0f/DH) - m1*m1;
    float rs0 = rsqrtf(var0 + LN_EPS), rs1 = rsqrtf(var1 + LN_EPS);

    int n0 = nodebase + w*16 + r, n1 = n0 + 8;
    #pragma unroll
    for (int nf = 0; nf < 16; nf++){
        int d0 = 8*nf + 2*c;
        float g0v = gms[d0], g1v = gms[d0+1], t0v = bts[d0], t1v = bts[d0+1];
        float a0 = acc[nf][0] + bps[d0],   a1v = acc[nf][1] + bps[d0+1];
        float a2 = acc[nf][2] + bps[d0],   a3v = acc[nf][3] + bps[d0+1];
        *(float2*)&g_enc[(size_t)n0*DH + d0] =
            make_float2((a0 - m0)*rs0*g0v + t0v, (a1v - m0)*rs0*g1v + t1v);
        *(float2*)&g_enc[(size_t)n1*DH + d0] =
            make_float2((a2 - m1)*rs1*g0v + t0v, (a3v - m1)*rs1*g1v + t1v);
    }
}

// ================= K5a: pooling partials (128 CTAs — parallel) ==============
__global__ __launch_bounds__(256) void k_pool(){
    int chunk = blockIdx.x, b = blockIdx.y;
    int t = threadIdx.x, d = t & 127, g2 = t >> 7;
    const float* eb = g_enc + (size_t)b*NN*DH;
    int n0 = chunk*125;
    float s = 0.f;
    for (int n = n0 + g2; n < n0 + 125; n += 2)
        s += eb[(size_t)n*DH + d];
    __shared__ float sh[128];
    if (g2 == 0) sh[d] = s;
    __syncthreads();
    if (g2 == 1) g_part[(b*16 + chunk)*DH + d] = sh[d] + s;
}

// ================= K5b: route emb + MLP head ================================
__global__ __launch_bounds__(256) void k_head2(const int* __restrict__ routes_raw,
        const float* __restrict__ W1, const float* __restrict__ b1,
        const float* __restrict__ W2, const float* __restrict__ b2,
        const float* __restrict__ Wv1, const float* __restrict__ bv1,
        const float* __restrict__ Wv2, const float* __restrict__ bv2,
        float* __restrict__ out){
    __shared__ float ge[DH], re[DH], comb[2*DH], h1[DH], h2[64], h3[32];
    __shared__ int ridx[RL];
    __shared__ float rvalid[RL];
    __shared__ unsigned notseen64;
    __shared__ float cnt_s;

    int b = blockIdx.x;
    int t = threadIdx.x;

    if (t == 0) notseen64 = 0u;
    __syncthreads();
    if (t < 200){
        int hi = routes_raw[2*t + 1];
        if (hi != 0 && hi != -1) atomicOr(&notseen64, 1u);
    }
    __syncthreads();
    int is64 = (notseen64 == 0u);
    if (t < RL){
        long long v;
        if (is64) v = ((const long long*)routes_raw)[b*RL + t];
        else      v = (long long)routes_raw[b*RL + t];
        ridx[t]   = (v < 0) ? 0 : (int)v;
        rvalid[t] = (v >= 0) ? 1.f : 0.f;
    }
    __syncthreads();

    int d = t & 127, g2 = t >> 7;
    const float* eb = g_enc + (size_t)b*NN*DH;
    float ga = 0.f;
    for (int cch = g2*8; cch < g2*8 + 8; cch++)
        ga += g_part[(b*16 + cch)*DH + d];
    float ra = 0.f;
    for (int lr = g2; lr < RL; lr += 2)
        ra += rvalid[lr] * eb[(size_t)ridx[lr]*DH + d];
    if (g2 == 0){ ge[d] = ga; re[d] = ra; }
    __syncthreads();
    if (g2 == 1){ ge[d] += ga; re[d] += ra; }
    if (t == 0){
        float cc = 0.f;
        for (int lr = 0; lr < RL; lr++) cc += rvalid[lr];
        cnt_s = cc;
    }
    __syncthreads();
    if (t < DH)        comb[t] = (cnt_s > 0.f) ? re[t] / fmaxf(cnt_s, 1.f) : 0.f;
    else if (t < 2*DH) comb[t] = ge[t - DH] * (1.0f/NN);
    __syncthreads();

    if (t < DH){
        float a = b1[t];
        for (int k = 0; k < 2*DH; k++) a = fmaf(comb[k], W1[k*DH + t], a);
        h1[t] = fmaxf(a, 0.f);
    }
    __syncthreads();
    if (t < 64){
        float a = b2[t];
        for (int k = 0; k < DH; k++) a = fmaf(h1[k], W2[k*64 + t], a);
        h2[t] = fmaxf(a, 0.f);
    }
    __syncthreads();
    if (t < 32){
        float a = bv1[t];
        for (int k = 0; k < 64; k++) a = fmaf(h2[k], Wv1[k*32 + t], a);
        h3[t] = fmaxf(a, 0.f);
    }
    __syncthreads();
    if (t < 3){
        float a = bv2[t];
        for (int k = 0; k < 32; k++) a = fmaf(h3[k], Wv2[k*3 + t], a);
        out[b*3 + t] = a;
    }
}

// ================= launch ===================================================
extern "C" void kernel_launch(void* const* d_in, const int* in_sizes, int n_in,
                              void* d_out, int out_size){
    (void)in_sizes; (void)n_in; (void)out_size;
    const float* nf     = (const float*)d_in[0];
    const int*   routes = (const int*)  d_in[1];
    const int*   adj    = (const int*)  d_in[2];
    const float* Wheads = (const float*)d_in[3];
    const float* a1     = (const float*)d_in[4];
    const float* a2     = (const float*)d_in[5];
    const float* Wp     = (const float*)d_in[6];
    const float* bp     = (const float*)d_in[7];
    const float* gamma  = (const float*)d_in[8];
    const float* beta   = (const float*)d_in[9];
    const float* W1     = (const float*)d_in[10];
    const float* b1     = (const float*)d_in[11];
    const float* W2     = (const float*)d_in[12];
    const float* b2     = (const float*)d_in[13];
    const float* Wv1    = (const float*)d_in[14];
    const float* bv1    = (const float*)d_in[15];
    const float* Wv2    = (const float*)d_in[16];
    const float* bv2    = (const float*)d_in[17];
    float* out = (float*)d_out;

    k_pack <<<NN, 256>>>(adj);
    k_wh   <<<dim3(63, BH), 256>>>(nf, Wheads, a1, a2);
    k_wpcvt<<<256, 256>>>(Wp);                 // keeps k_attn at profiled slot
    k_attn <<<dim3(NMT, BH), 256>>>();
    k_proj <<<125, 256>>>(bp, gamma, beta);
    k_pool <<<dim3(16, BB), 256>>>();
    k_head2<<<BB, 256>>>(routes, W1, b1, W2, b2, Wv1, bv1, Wv2, bv2, out);
}

// round 17
// speedup vs baseline: 1.3796x; 1.2886x over previous
#include <cuda_runtime.h>
#include <cuda_fp16.h>
#include <cstdint>
#include <math.h>

#define NN   2000
#define NNP  2048      // padded j-dim for WhT (covers 32 tiles of 64)
#define BB   8
#define HH   4
#define DIN  64
#define DH   128
#define BH   32        // BB*HH
#define RL   50
#define MT   128       // M tile (rows per CTA) for attn and wh
#define NMT  16        // ceil(2000/128)
#define JT2  64        // attention j tile
#define NJT2 32        // 2048/64
#define LOG2E 1.4426950408889634f
#define LN_EPS 1e-5f
#define BPAD 40        // k_proj smem row stride in halves
#define BPAD2 72       // smem tile row stride in halves (64 + 8 pad)
#define WPK  520       // WpT row stride in halves (512 + 8 pad)
#define ONES2 0x3C003C00u   // two f16 1.0

// ---------------- device scratch (static; zero-initialized at load) ---------
__device__ __half   g_WhTH[(size_t)BH*DH*NNP];   // [(bh*128+d)][j] transposed Wh, f16
__device__ __half   g_XH  [(size_t)BB*2048*DIN]; // node features f16, node-padded
__device__ __half   g_WTH [HH*DH*DIN];           // W^T f16 [h][n][k]
__device__ float    g_f1 [BH*NN];
__device__ float    g_f2 [BH*NN];
__device__ unsigned g_adjT[64*2048];             // [tile32][row] packed adjacency
__device__ int      g_hasnbr[NN];
__device__ __half   g_hpH[(size_t)BB*NN*HH*DH];  // elu(h_prime) node-major, f16
__device__ __half   g_WpTH[DH*WPK];              // WpT [n][k] f16
__device__ float    g_enc[(size_t)BB*NN*DH];
__device__ float    g_part[BB*16*DH];            // pooling partials

// ---------------- helpers ----------------------------------------------------
__device__ __forceinline__ uint32_t packh2(float lo, float hi){
    __half2 h = __floats2half2_rn(lo, hi);
    return *reinterpret_cast<uint32_t*>(&h);
}
__device__ __forceinline__ float ex2f(float x){
    float r; asm("ex2.approx.ftz.f32 %0, %1;" : "=f"(r) : "f"(x)); return r;
}
__device__ __forceinline__ uint32_t ex2h2(uint32_t a){
    uint32_t r; asm("ex2.approx.f16x2 %0, %1;" : "=r"(r) : "r"(a)); return r;
}
__device__ __forceinline__ uint32_t prmtb(uint32_t a, uint32_t b, uint32_t s){
    uint32_t d; asm("prmt.b32 %0, %1, %2, %3;" : "=r"(d) : "r"(a), "r"(b), "r"(s));
    return d;
}
__device__ __forceinline__ uint32_t smem_u32(const void* p){
    uint32_t a;
    asm("{ .reg .u64 t; cvta.to.shared.u64 t, %1; cvt.u32.u64 %0, t; }"
        : "=r"(a) : "l"(p));
    return a;
}
__device__ __forceinline__ unsigned long long add2(unsigned long long a,
                                                   unsigned long long b){
    unsigned long long d;
    asm("add.rn.f32x2 %0, %1, %2;" : "=l"(d) : "l"(a), "l"(b));
    return d;
}
__device__ __forceinline__ unsigned long long ffma2(unsigned long long a,
                                                    unsigned long long b,
                                                    unsigned long long c){
    unsigned long long d;
    asm("fma.rn.f32x2 %0, %1, %2, %3;" : "=l"(d) : "l"(a), "l"(b), "l"(c));
    return d;
}
__device__ __forceinline__ unsigned long long packdup(float p){
    unsigned long long d;
    asm("mov.b64 %0, {%1, %2};" : "=l"(d) : "f"(p), "f"(p));
    return d;
}
__device__ __forceinline__ float u64lo(unsigned long long v){
    return __uint_as_float((unsigned)(v & 0xffffffffULL));
}
__device__ __forceinline__ float u64hi(unsigned long long v){
    return __uint_as_float((unsigned)(v >> 32));
}
__device__ __forceinline__ void mma_f16(float* c, const uint32_t* a,
                                        uint32_t b0, uint32_t b1){
    asm volatile("mma.sync.aligned.m16n8k16.row.col.f32.f16.f16.f32 "
        "{%0,%1,%2,%3}, {%4,%5,%6,%7}, {%8,%9}, {%0,%1,%2,%3};"
        : "+f"(c[0]), "+f"(c[1]), "+f"(c[2]), "+f"(c[3])
        : "r"(a[0]), "r"(a[1]), "r"(a[2]), "r"(a[3]), "r"(b0), "r"(b1));
}
__device__ __forceinline__ void ldsm_x4(uint32_t& r0, uint32_t& r1,
                                        uint32_t& r2, uint32_t& r3, uint32_t a){
    asm volatile("ldmatrix.sync.aligned.m8n8.x4.shared.b16 {%0,%1,%2,%3}, [%4];"
        : "=r"(r0), "=r"(r1), "=r"(r2), "=r"(r3) : "r"(a));
}
#define CPA16(s,g)   asm volatile("cp.async.cg.shared.global [%0], [%1], 16;" :: "r"(s), "l"(g))
#define CPA_COMMIT() asm volatile("cp.async.commit_group;" ::: "memory")
#define CPA_WAIT0()  asm volatile("cp.async.wait_group 0;" ::: "memory")

// ==== K0: pack adjacency (transposed) — int4 loads + shfl-OR assembly =======
__global__ __launch_bounds__(256) void k_pack(const int* __restrict__ adj){
    int i = blockIdx.x;
    int t = threadIdx.x;
    int w = t >> 5, l = t & 31;
    __shared__ unsigned orr;
    if (t == 0) orr = 0u;
    __syncthreads();

    const int* rowp = adj + (size_t)i*NN;
    unsigned wor = 0u;
    #pragma unroll
    for (int pass = 0; pass < 2; pass++){
        int j = pass*1024 + w*128 + l*4;
        unsigned nib = 0u;
        if (j < NN){
            int4 v4 = *(const int4*)(rowp + j);
            nib  = (v4.x > 0) ? 1u : 0u;
            nib |= (v4.y > 0) ? 2u : 0u;
            nib |= (v4.z > 0) ? 4u : 0u;
            nib |= (v4.w > 0) ? 8u : 0u;
        }
        unsigned v = nib << ((l & 7)*4);
        v |= __shfl_xor_sync(0xffffffffu, v, 1);
        v |= __shfl_xor_sync(0xffffffffu, v, 2);
        v |= __shfl_xor_sync(0xffffffffu, v, 4);
        if ((l & 7) == 0){
            int g = pass*32 + w*4 + (l >> 3);
            g_adjT[g*2048 + i] = v;
            wor |= v;
        }
    }
    if ((l & 7) == 0 && wor) atomicOr(&orr, 1u);
    __syncthreads();
    if (t == 0) g_hasnbr[i] = (orr != 0u);
}

// ================= K2: WpT f16 conversion ===================================
__global__ __launch_bounds__(256) void k_wpcvt(const float* __restrict__ Wp){
    int id = blockIdx.x*256 + threadIdx.x;
    if (id < 512*128){
        int k = id >> 7, n = id & 127;
        g_WpTH[n*WPK + k] = __float2half_rn(Wp[id]);
    }
}

// ===== K_cvt: X -> f16 (node-padded) and W_heads -> WT f16 ==================
__global__ __launch_bounds__(256) void k_cvt(const float* __restrict__ nf,
                                             const float* __restrict__ Wheads){
    int bx = blockIdx.x, t = threadIdx.x;
    if (bx < 64){
        int b = bx >> 3, nb = (bx & 7)*250;
        for (int q = 0; q < 63; q++){
            int idx = q*256 + t;
            if (idx < 250*64){
                int node = nb + (idx >> 6), k = idx & 63;
                g_XH[((size_t)(b*2048 + node) << 6) + k] =
                    __float2half_rn(nf[((size_t)(b*2000 + node) << 6) + k]);
            }
        }
    } else {
        int h = bx - 64;
        for (int q = 0; q < 32; q++){
            int idx = q*256 + t;          // 8192 = 128n x 64k
            int n = idx >> 6, k = idx & 63;
            g_WTH[h*8192 + idx] = __float2half_rn(Wheads[(h*64 + k)*128 + n]);
        }
    }
}

// ===== K1: Wh via f16 MMA; emits WhT f16 + f1/f2 (f32 accumulators) =========
__global__ __launch_bounds__(256) void k_wh(const float* __restrict__ a1,
                                            const float* __restrict__ a2){
    __shared__ __align__(16) __half sbuf[2*DH*BPAD2];   // X | WT; reused for WhT
    __shared__ float a1s[DH], a2s[DH];

    int bh = blockIdx.y;
    int h = bh & 3, b = bh >> 2;
    int rowbase = blockIdx.x * MT;
    int t = threadIdx.x, w = t >> 5, l = t & 31;
    int c = l & 3, r = l >> 2;

    uint32_t xs = smem_u32(sbuf);
    uint32_t ws = xs + DH*BPAD2*2;

    const __half* Xg = g_XH + ((size_t)(b*2048 + rowbase) << 6);
    const __half* Wg = g_WTH + h*8192;
    #pragma unroll
    for (int i = 0; i < 8; i++){
        int chunk = t + 256*i;
        if (chunk < 1024){
            int row = chunk >> 3, seg = chunk & 7;
            CPA16(xs + row*(BPAD2*2) + seg*16, Xg + row*64 + seg*8);
        } else {
            int c2 = chunk - 1024, row = c2 >> 3, seg = c2 & 7;
            CPA16(ws + row*(BPAD2*2) + seg*16, Wg + row*64 + seg*8);
        }
    }
    CPA_COMMIT();
    if (t < DH){ a1s[t] = a1[h*DH + t]; a2s[t] = a2[h*DH + t]; }
    CPA_WAIT0();
    __syncthreads();

    // A fragments (X rows): 4 k-steps of 16
    uint32_t afr[4][4];
    uint32_t aaddr = xs + 2u*((w*16 + (l & 15))*BPAD2 + (l >> 4)*8);
    #pragma unroll
    for (int ks = 0; ks < 4; ks++)
        ldsm_x4(afr[ks][0], afr[ks][1], afr[ks][2], afr[ks][3], aaddr + ks*32);

    float acc[16][4];
    #pragma unroll
    for (int nf2 = 0; nf2 < 16; nf2++)
        #pragma unroll
        for (int q = 0; q < 4; q++) acc[nf2][q] = 0.f;

    uint32_t bbase = ws + 2u*((l & 7)*BPAD2 + (l >> 3)*8);
    #pragma unroll
    for (int nf2 = 0; nf2 < 16; nf2++){
        uint32_t ad = bbase + nf2*(8*BPAD2*2);
        uint32_t b0, b1, b2, b3, b4, b5, b6, b7;
        ldsm_x4(b0, b1, b2, b3, ad);
        ldsm_x4(b4, b5, b6, b7, ad + 64);
        mma_f16(acc[nf2], afr[0], b0, b1);
        mma_f16(acc[nf2], afr[1], b2, b3);
        mma_f16(acc[nf2], afr[2], b4, b5);
        mma_f16(acc[nf2], afr[3], b6, b7);
    }

    // f1/f2 from f32 accumulators
    int gr0 = rowbase + w*16 + r, gr1 = gr0 + 8;
    float f1p0 = 0.f, f2p0 = 0.f, f1p1 = 0.f, f2p1 = 0.f;
    #pragma unroll
    for (int nf2 = 0; nf2 < 16; nf2++){
        int d0 = 8*nf2 + 2*c;
        float w1a = a1s[d0], w1b = a1s[d0+1];
        float w2a = a2s[d0], w2b = a2s[d0+1];
        f1p0 = fmaf(acc[nf2][0], w1a, fmaf(acc[nf2][1], w1b, f1p0));
        f2p0 = fmaf(acc[nf2][0], w2a, fmaf(acc[nf2][1], w2b, f2p0));
        f1p1 = fmaf(acc[nf2][2], w1a, fmaf(acc[nf2][3], w1b, f1p1));
        f2p1 = fmaf(acc[nf2][2], w2a, fmaf(acc[nf2][3], w2b, f2p1));
    }
    #pragma unroll
    for (int off = 1; off <= 2; off <<= 1){
        f1p0 += __shfl_xor_sync(0xffffffffu, f1p0, off);
        f2p0 += __shfl_xor_sync(0xffffffffu, f2p0, off);
        f1p1 += __shfl_xor_sync(0xffffffffu, f1p1, off);
        f2p1 += __shfl_xor_sync(0xffffffffu, f2p1, off);
    }
    if (c == 0){
        if (gr0 < NN){ g_f1[bh*NN + gr0] = f1p0; g_f2[bh*NN + gr0] = f2p0; }
        if (gr1 < NN){ g_f1[bh*NN + gr1] = f1p1; g_f2[bh*NN + gr1] = f2p1; }
    }

    // transpose: stage acc as f16 [d][row] (stride 144 halves) in reused sbuf
    __syncthreads();
    __half* smt = sbuf;
    int r0l = w*16 + r, r1l = r0l + 8;
    #pragma unroll
    for (int nf2 = 0; nf2 < 16; nf2++){
        int d0 = 8*nf2 + 2*c;
        smt[d0*144 + r0l]       = __float2half_rn(acc[nf2][0]);
        smt[(d0+1)*144 + r0l]   = __float2half_rn(acc[nf2][1]);
        smt[d0*144 + r1l]       = __float2half_rn(acc[nf2][2]);
        smt[(d0+1)*144 + r1l]   = __float2half_rn(acc[nf2][3]);
    }
    __syncthreads();
    {
        int d = t >> 1, hf2 = t & 1;
        const __half* src = smt + d*144 + hf2*64;
        __half* dst = g_WhTH + ((size_t)bh*DH + d)*NNP + rowbase + hf2*64;
        #pragma unroll
        for (int q = 0; q < 8; q++)
            *(uint4*)(dst + q*8) = *(const uint4*)(src + q*8);
    }
}

// ====== K3: fused attention via mma.sync f16 (R16, unchanged) ===============
__global__ __launch_bounds__(256,2) void k_attn(){
    __shared__ __align__(16) float  f2a[NNP];
    __shared__ __align__(16) __half Whs[2][DH*BPAD2];   // 2 x 18432 B
    __shared__ float  redm[8];

    int bh = blockIdx.y;
    int b = bh >> 2, h = bh & 3;
    int rowbase = blockIdx.x * MT;
    int t = threadIdx.x, w = t >> 5, l = t & 31;
    int c = l & 3, r = l >> 2;

    const __half* WhTb = g_WhTH + (size_t)bh*DH*NNP;
    uint32_t whs_u32 = smem_u32(&Whs[0][0]);
    uint32_t lofs = 2u*((l & 7)*BPAD2 + (l >> 3)*8);

    #pragma unroll
    for (int i = 0; i < 4; i++){
        int chunk = t + 256*i;
        int row = chunk >> 3, seg = chunk & 7;
        CPA16(whs_u32 + row*(BPAD2*2) + seg*16,
              WhTb + (size_t)row*NNP + seg*8);
    }
    CPA_COMMIT();

    const float* f2b = g_f2 + bh*NN;
    float lm = -3.0e38f;
    #pragma unroll
    for (int i = 0; i < 8; i++){
        int idx = t + 256*i;
        float v = (idx < NN) ? f2b[idx]*LOG2E : 0.f;
        f2a[idx] = v;
        if (idx < NN) lm = fmaxf(lm, v);
    }
    #pragma unroll
    for (int off = 16; off; off >>= 1)
        lm = fmaxf(lm, __shfl_xor_sync(0xffffffffu, lm, off));
    if (l == 0) redm[w] = lm;
    CPA_WAIT0();
    __syncthreads();

    float M2L = redm[0];
    #pragma unroll
    for (int q = 1; q < 8; q++) M2L = fmaxf(M2L, redm[q]);

    int gr0 = rowbase + w*16 + r, gr1 = gr0 + 8;
    bool v0 = gr0 < NN, v1 = gr1 < NN;
    float c1_0 = 0.f, c2_0 = 0.f, c1_1 = 0.f, c2_1 = 0.f;
    int uf0 = 0, uf1 = 0;
    if (v0){
        float f1L = g_f1[bh*NN + gr0]*LOG2E;
        float tL = f1L + M2L, mL = fmaxf(tL, 0.2f*tL);
        c1_0 = f1L - mL; c2_0 = 0.2f*f1L - mL;
        uf0 = (g_hasnbr[gr0] == 0);
    }
    if (v1){
        float f1L = g_f1[bh*NN + gr1]*LOG2E;
        float tL = f1L + M2L, mL = fmaxf(tL, 0.2f*tL);
        c1_1 = f1L - mL; c2_1 = 0.2f*f1L - mL;
        uf1 = (g_hasnbr[gr1] == 0);
    }
    bool anyuf = __any_sync(0xffffffffu, (uf0 | uf1) != 0);

    unsigned long long c1p0 = packdup(c1_0), c2p0 = packdup(c2_0);
    unsigned long long c1p1 = packdup(c1_1), c2p1 = packdup(c2_1);
    unsigned long long k02  = packdup(0.2f);
    int shc = 2*c;

    float acc[16][4];
    #pragma unroll
    for (int nf = 0; nf < 16; nf++)
        #pragma unroll
        for (int q = 0; q < 4; q++) acc[nf][q] = 0.f;
    float accS[4] = {0.f, 0.f, 0.f, 0.f};

    for (int tile = 0; tile < NJT2; tile++){
        bool more = (tile + 1 < NJT2);
        int t32a = 2*tile, t32b = 2*tile + 1;
        unsigned awr[2][2];
        awr[0][0] = v0 ? g_adjT[t32a*2048 + gr0] : 0u;
        awr[0][1] = v1 ? g_adjT[t32a*2048 + gr1] : 0u;
        awr[1][0] = v0 ? g_adjT[t32b*2048 + gr0] : 0u;
        awr[1][1] = v1 ? g_adjT[t32b*2048 + gr1] : 0u;

        if (more){
            int j0n = (tile + 1)*JT2;
            uint32_t sb = whs_u32 + ((tile + 1) & 1)*(DH*BPAD2*2);
            #pragma unroll
            for (int i = 0; i < 4; i++){
                int chunk = t + 256*i;
                int row = chunk >> 3, seg = chunk & 7;
                CPA16(sb + row*(BPAD2*2) + seg*16,
                      WhTb + (size_t)row*NNP + j0n + seg*8);
            }
            CPA_COMMIT();
        }

        uint32_t cb = whs_u32 + (tile & 1)*(DH*BPAD2*2);
        #pragma unroll
        for (int sub = 0; sub < 2; sub++){
            int j0s = (2*tile + sub)*32;
            unsigned aw0 = awr[sub][0], aw1 = awr[sub][1];

            uint32_t u0  = (aw0 >> shc) << 6, u0b = u0 << 1;
            uint32_t u1  = (aw1 >> shc) << 6, u1b = u1 << 1;
            uint32_t m0A0 = prmtb(u0b, u0, 0xCC88), m0B0 = prmtb(u0b, u0, 0xDD99);
            uint32_t m0A1 = prmtb(u0b, u0, 0xEEAA), m0B1 = prmtb(u0b, u0, 0xFFBB);
            uint32_t m1A0 = prmtb(u1b, u1, 0xCC88), m1B0 = prmtb(u1b, u1, 0xDD99);
            uint32_t m1A1 = prmtb(u1b, u1, 0xEEAA), m1B1 = prmtb(u1b, u1, 0xFFBB);

            uint32_t afr[2][4];
            #pragma unroll
            for (int ks = 0; ks < 2; ks++){
                int j1 = 16*ks + shc;
                unsigned long long fpA = *(const unsigned long long*)&f2a[j0s + j1];
                unsigned long long fpB = *(const unsigned long long*)&f2a[j0s + j1 + 8];
                unsigned long long uA0 = add2(fpA, c1p0);
                unsigned long long tA0 = ffma2(fpA, k02, c2p0);
                unsigned long long uB0 = add2(fpB, c1p0);
                unsigned long long tB0 = ffma2(fpB, k02, c2p0);
                float a00 = fmaxf(u64lo(uA0), u64lo(tA0));
                float a01 = fmaxf(u64hi(uA0), u64hi(tA0));
                float a08 = fmaxf(u64lo(uB0), u64lo(tB0));
                float a09 = fmaxf(u64hi(uB0), u64hi(tB0));
                unsigned long long uA1 = add2(fpA, c1p1);
                unsigned long long tA1 = ffma2(fpA, k02, c2p1);
                unsigned long long uB1 = add2(fpB, c1p1);
                unsigned long long tB1 = ffma2(fpB, k02, c2p1);
                float b00 = fmaxf(u64lo(uA1), u64lo(tA1));
                float b01 = fmaxf(u64hi(uA1), u64hi(tA1));
                float b08 = fmaxf(u64lo(uB1), u64lo(tB1));
                float b09 = fmaxf(u64hi(uB1), u64hi(tB1));
                uint32_t p0A = ex2h2(packh2(a00, a01)) & (ks ? m0A1 : m0A0);
                uint32_t p1A = ex2h2(packh2(b00, b01)) & (ks ? m1A1 : m1A0);
                uint32_t p0B = ex2h2(packh2(a08, a09)) & (ks ? m0B1 : m0B0);
                uint32_t p1B = ex2h2(packh2(b08, b09)) & (ks ? m1B1 : m1B0);
                if (anyuf){
                    if (uf0){
                        uint32_t hA = ((j0s+j1   < NN) ? 0x3C00u : 0u)
                                    | ((j0s+j1+1 < NN) ? 0x3C000000u : 0u);
                        uint32_t hB = ((j0s+j1+8 < NN) ? 0x3C00u : 0u)
                                    | ((j0s+j1+9 < NN) ? 0x3C000000u : 0u);
                        p0A = hA; p0B = hB;
                    }
                    if (uf1){
                        uint32_t hA = ((j0s+j1   < NN) ? 0x3C00u : 0u)
                                    | ((j0s+j1+1 < NN) ? 0x3C000000u : 0u);
                        uint32_t hB = ((j0s+j1+8 < NN) ? 0x3C00u : 0u)
                                    | ((j0s+j1+9 < NN) ? 0x3C000000u : 0u);
                        p1A = hA; p1B = hB;
                    }
                }
                afr[ks][0] = p0A; afr[ks][1] = p1A;
                afr[ks][2] = p0B; afr[ks][3] = p1B;
            }

            mma_f16(accS, afr[0], ONES2, ONES2);
            mma_f16(accS, afr[1], ONES2, ONES2);

            uint32_t abase = cb + sub*64 + lofs;
            #pragma unroll
            for (int nf = 0; nf < 16; nf++){
                uint32_t b0, b1, b2, b3;
                ldsm_x4(b0, b1, b2, b3, abase + nf*(8*BPAD2*2));
                mma_f16(acc[nf], afr[0], b0, b1);
                mma_f16(acc[nf], afr[1], b2, b3);
            }
        }

        if (more) CPA_WAIT0();
        __syncthreads();
    }

    float r0inv = (v0 && accS[0] != 0.f) ? 1.0f/accS[0] : 0.f;
    float r1inv = (v1 && accS[2] != 0.f) ? 1.0f/accS[2] : 0.f;

    __half* hp0 = v0 ? &g_hpH[(((size_t)b*NN + gr0)*HH + h)*DH] : nullptr;
    __half* hp1 = v1 ? &g_hpH[(((size_t)b*NN + gr1)*HH + h)*DH] : nullptr;
    #pragma unroll
    for (int nf = 0; nf < 16; nf++){
        int d0 = 8*nf + 2*c;
        if (v0){
            float e0 = acc[nf][0]*r0inv;
            e0 = (e0 > 0.f) ? e0 : ex2f(e0*LOG2E) - 1.0f;
            float e1 = acc[nf][1]*r0inv;
            e1 = (e1 > 0.f) ? e1 : ex2f(e1*LOG2E) - 1.0f;
            *(uint32_t*)(hp0 + d0) = packh2(e0, e1);
        }
        if (v1){
            float e2 = acc[nf][2]*r1inv;
            e2 = (e2 > 0.f) ? e2 : ex2f(e2*LOG2E) - 1.0f;
            float e3 = acc[nf][3]*r1inv;
            e3 = (e3 > 0.f) ? e3 : ex2f(e3*LOG2E) - 1.0f;
            *(uint32_t*)(hp1 + d0) = packh2(e2, e3);
        }
    }
}

// ========== K4: g_enc = LN(elu(concat) @ Wp + bp) (cp.async double-buffer) ==
__global__ __launch_bounds__(256) void k_proj(const float* __restrict__ bp,
                                              const float* __restrict__ gamma,
                                              const float* __restrict__ beta){
    __shared__ __align__(16) __half As[2][DH*BPAD];
    __shared__ __align__(16) __half Bs[2][DH*BPAD];
    __shared__ float bps[DH], gms[DH], bts[DH];
    int nodebase = blockIdx.x * 128;
    int t = threadIdx.x, w = t >> 5, l = t & 31;
    int c = l & 3, r = l >> 2;
    int dq = t >> 1, seg = t & 1;

    if (t < DH){ bps[t] = bp[t]; gms[t] = gamma[t]; bts[t] = beta[t]; }

    float acc[16][4];
    #pragma unroll
    for (int nf = 0; nf < 16; nf++)
        #pragma unroll
        for (int q = 0; q < 4; q++) acc[nf][q] = 0.f;

    const __half* Ab = g_hpH + (size_t)nodebase*512;
    uint32_t as0 = smem_u32(&As[0][0]);
    uint32_t bs0 = smem_u32(&Bs[0][0]);
    const int BUFB = DH*BPAD*2;
    uint32_t sofs = 2u*(dq*BPAD + seg*16);

    {
        const __half* ga = Ab + (size_t)dq*512 + seg*16;
        const __half* gb = g_WpTH + dq*WPK + seg*16;
        CPA16(as0 + sofs, ga); CPA16(as0 + sofs + 16, ga + 8);
        CPA16(bs0 + sofs, gb); CPA16(bs0 + sofs + 16, gb + 8);
        CPA_COMMIT();
    }

    for (int kc = 0; kc < 16; kc++){
        CPA_WAIT0();
        __syncthreads();
        if (kc + 1 < 16){
            int nb = (kc + 1) & 1;
            const __half* ga = Ab + (size_t)dq*512 + (kc+1)*32 + seg*16;
            const __half* gb = g_WpTH + dq*WPK + (kc+1)*32 + seg*16;
            CPA16(as0 + nb*BUFB + sofs, ga); CPA16(as0 + nb*BUFB + sofs + 16, ga + 8);
            CPA16(bs0 + nb*BUFB + sofs, gb); CPA16(bs0 + nb*BUFB + sofs + 16, gb + 8);
            CPA_COMMIT();
        }
        const __half* Ac = As[kc & 1];
        const __half* Bc = Bs[kc & 1];

        #pragma unroll
        for (int ks = 0; ks < 2; ks++){
            uint32_t af[4];
            af[0] = *(const uint32_t*)&Ac[(w*16 + r    )*BPAD + 16*ks + 2*c];
            af[1] = *(const uint32_t*)&Ac[(w*16 + r + 8)*BPAD + 16*ks + 2*c];
            af[2] = *(const uint32_t*)&Ac[(w*16 + r    )*BPAD + 16*ks + 2*c + 8];
            af[3] = *(const uint32_t*)&Ac[(w*16 + r + 8)*BPAD + 16*ks + 2*c + 8];
            #pragma unroll
            for (int nf = 0; nf < 16; nf++){
                const __half* bpp = &Bc[(8*nf + r)*BPAD + 16*ks + 2*c];
                mma_f16(acc[nf], af, *(const uint32_t*)bpp, *(const uint32_t*)(bpp + 8));
            }
        }
    }

    float s0 = 0.f, q0 = 0.f, s1 = 0.f, q1 = 0.f;
    #pragma unroll
    for (int nf = 0; nf < 16; nf++){
        int d0 = 8*nf + 2*c;
        float a0 = acc[nf][0] + bps[d0],   a1v = acc[nf][1] + bps[d0+1];
        float a2 = acc[nf][2] + bps[d0],   a3v = acc[nf][3] + bps[d0+1];
        s0 += a0 + a1v;  q0 += a0*a0 + a1v*a1v;
        s1 += a2 + a3v;  q1 += a2*a2 + a3v*a3v;
    }
    #pragma unroll
    for (int off = 1; off <= 2; off <<= 1){
        s0 += __shfl_xor_sync(0xffffffffu, s0, off);
        q0 += __shfl_xor_sync(0xffffffffu, q0, off);
        s1 += __shfl_xor_sync(0xffffffffu, s1, off);
        q1 += __shfl_xor_sync(0xffffffffu, q1, off);
    }
    float m0 = s0*(1.0f/DH), var0 = q0*(1.0f/DH) - m0*m0;
    float m1 = s1*(1.0f/DH), var1 = q1*(1.0f/DH) - m1*m1;
    float rs0 = rsqrtf(var0 + LN_EPS), rs1 = rsqrtf(var1 + LN_EPS);

    int n0 = nodebase + w*16 + r, n1 = n0 + 8;
    #pragma unroll
    for (int nf = 0; nf < 16; nf++){
        int d0 = 8*nf + 2*c;
        float g0v = gms[d0], g1v = gms[d0+1], t0v = bts[d0], t1v = bts[d0+1];
        float a0 = acc[nf][0] + bps[d0],   a1v = acc[nf][1] + bps[d0+1];
        float a2 = acc[nf][2] + bps[d0],   a3v = acc[nf][3] + bps[d0+1];
        *(float2*)&g_enc[(size_t)n0*DH + d0] =
            make_float2((a0 - m0)*rs0*g0v + t0v, (a1v - m0)*rs0*g1v + t1v);
        *(float2*)&g_enc[(size_t)n1*DH + d0] =
            make_float2((a2 - m1)*rs1*g0v + t0v, (a3v - m1)*rs1*g1v + t1v);
    }
}

// ================= K5a: pooling partials (128 CTAs — parallel) ==============
__global__ __launch_bounds__(256) void k_pool(){
    int chunk = blockIdx.x, b = blockIdx.y;
    int t = threadIdx.x, d = t & 127, g2 = t >> 7;
    const float* eb = g_enc + (size_t)b*NN*DH;
    int n0 = chunk*125;
    float s = 0.f;
    for (int n = n0 + g2; n < n0 + 125; n += 2)
        s += eb[(size_t)n*DH + d];
    __shared__ float sh[128];
    if (g2 == 0) sh[d] = s;
    __syncthreads();
    if (g2 == 1) g_part[(b*16 + chunk)*DH + d] = sh[d] + s;
}

// ================= K5b: route emb + MLP head ================================
__global__ __launch_bounds__(256) void k_head2(const int* __restrict__ routes_raw,
        const float* __restrict__ W1, const float* __restrict__ b1,
        const float* __restrict__ W2, const float* __restrict__ b2,
        const float* __restrict__ Wv1, const float* __restrict__ bv1,
        const float* __restrict__ Wv2, const float* __restrict__ bv2,
        float* __restrict__ out){
    __shared__ float ge[DH], re[DH], comb[2*DH], h1[DH], h2[64], h3[32];
    __shared__ int ridx[RL];
    __shared__ float rvalid[RL];
    __shared__ unsigned notseen64;
    __shared__ float cnt_s;

    int b = blockIdx.x;
    int t = threadIdx.x;

    if (t == 0) notseen64 = 0u;
    __syncthreads();
    if (t < 200){
        int hi = routes_raw[2*t + 1];
        if (hi != 0 && hi != -1) atomicOr(&notseen64, 1u);
    }
    __syncthreads();
    int is64 = (notseen64 == 0u);
    if (t < RL){
        long long v;
        if (is64) v = ((const long long*)routes_raw)[b*RL + t];
        else      v = (long long)routes_raw[b*RL + t];
        ridx[t]   = (v < 0) ? 0 : (int)v;
        rvalid[t] = (v >= 0) ? 1.f : 0.f;
    }
    __syncthreads();

    int d = t & 127, g2 = t >> 7;
    const float* eb = g_enc + (size_t)b*NN*DH;
    float ga = 0.f;
    for (int cch = g2*8; cch < g2*8 + 8; cch++)
        ga += g_part[(b*16 + cch)*DH + d];
    float ra = 0.f;
    for (int lr = g2; lr < RL; lr += 2)
        ra += rvalid[lr] * eb[(size_t)ridx[lr]*DH + d];
    if (g2 == 0){ ge[d] = ga; re[d] = ra; }
    __syncthreads();
    if (g2 == 1){ ge[d] += ga; re[d] += ra; }
    if (t == 0){
        float cc = 0.f;
        for (int lr = 0; lr < RL; lr++) cc += rvalid[lr];
        cnt_s = cc;
    }
    __syncthreads();
    if (t < DH)        comb[t] = (cnt_s > 0.f) ? re[t] / fmaxf(cnt_s, 1.f) : 0.f;
    else if (t < 2*DH) comb[t] = ge[t - DH] * (1.0f/NN);
    __syncthreads();

    if (t < DH){
        float a = b1[t];
        for (int k = 0; k < 2*DH; k++) a = fmaf(comb[k], W1[k*DH + t], a);
        h1[t] = fmaxf(a, 0.f);
    }
    __syncthreads();
    if (t < 64){
        float a = b2[t];
        for (int k = 0; k < DH; k++) a = fmaf(h1[k], W2[k*64 + t], a);
        h2[t] = fmaxf(a, 0.f);
    }
    __syncthreads();
    if (t < 32){
        float a = bv1[t];
        for (int k = 0; k < 64; k++) a = fmaf(h2[k], Wv1[k*32 + t], a);
        h3[t] = fmaxf(a, 0.f);
    }
    __syncthreads();
    if (t < 3){
        float a = bv2[t];
        for (int k = 0; k < 32; k++) a = fmaf(h3[k], Wv2[k*3 + t], a);
        out[b*3 + t] = a;
    }
}

// ================= launch ===================================================
extern "C" void kernel_launch(void* const* d_in, const int* in_sizes, int n_in,
                              void* d_out, int out_size){
    (void)in_sizes; (void)n_in; (void)out_size;
    const float* nf     = (const float*)d_in[0];
    const int*   routes = (const int*)  d_in[1];
    const int*   adj    = (const int*)  d_in[2];
    const float* Wheads = (const float*)d_in[3];
    const float* a1     = (const float*)d_in[4];
    const float* a2     = (const float*)d_in[5];
    const float* Wp     = (const float*)d_in[6];
    const float* bp     = (const float*)d_in[7];
    const float* gamma  = (const float*)d_in[8];
    const float* beta   = (const float*)d_in[9];
    const float* W1     = (const float*)d_in[10];
    const float* b1     = (const float*)d_in[11];
    const float* W2     = (const float*)d_in[12];
    const float* b2     = (const float*)d_in[13];
    const float* Wv1    = (const float*)d_in[14];
    const float* bv1    = (const float*)d_in[15];
    const float* Wv2    = (const float*)d_in[16];
    const float* bv2    = (const float*)d_in[17];
    float* out = (float*)d_out;

    k_pack <<<NN, 256>>>(adj);
    k_wpcvt<<<256, 256>>>(Wp);
    k_cvt  <<<68, 256>>>(nf, Wheads);
    k_wh   <<<dim3(NMT, BH), 256>>>(a1, a2);   // profiled slot: new MMA k_wh
    k_attn <<<dim3(NMT, BH), 256>>>();
    k_proj <<<125, 256>>>(bp, gamma, beta);
    k_pool <<<dim3(16, BB), 256>>>();
    k_head2<<<BB, 256>>>(routes, W1, b1, W2, b2, Wv1, bv1, Wv2, bv2, out);
}